// round 7
// baseline (speedup 1.0000x reference)
#include <cuda_runtime.h>
#include <cuda_bf16.h>

#define PH    16
#define PW    16
#define NM    16
#define HDIM  224
#define WDIM  224
#define CDIM  64
#define HW    (HDIM * WDIM)

// CTA = 2 horizontally adjacent 16x16 patches, processed pipelined:
// stores of patch k interleave with the channel-load stream of patch k+1.
__global__ __launch_bounds__(256, 5)
void msp_dct_kernel(const float* __restrict__ x,
                    const float* __restrict__ bases,
                    float* __restrict__ out) {
    __shared__ float4 sPart[256];
    __shared__ float  sW[2][NM];
    __shared__ float  sCoef[NM];

    const int t   = threadIdx.x;
    const int pwg = blockIdx.x;          // 0..6 (pair of patches)
    const int ph  = blockIdx.y;          // 0..13
    const int b   = blockIdx.z;          // 0..15
    const int h0  = ph * PH;

    const int g   = t & 63;              // pixel quad 0..63
    const int pi  = g >> 2;
    const int pj4 = (g & 3) * 4;
    const int csl = t >> 6;              // channel slice 0..3

    // store-batch decomposition (constant across iterations)
    int sm[4], sii[4], sjj[4];
    #pragma unroll
    for (int k = 0; k < 4; k++) {
        const int idx = t + k * 256;     // 0..1023
        sm[k]  = idx >> 6;
        sii[k] = (idx & 63) >> 2;
        sjj[k] = (idx & 3) * 4;
    }

    const float* xbase = x + ((size_t)(b * CDIM + csl * 16)) * HW
                           + (size_t)(h0 + pi) * WDIM + pj4;
    float* obase = out + ((size_t)b * NM) * HW;

    int w0p = 0;                         // previous patch left edge

    #pragma unroll
    for (int it = 0; it < 2; it++) {
        const int w0 = (pwg * 2 + it) * PW;
        const float* p = xbase + w0;

        float4 acc = make_float4(0.f, 0.f, 0.f, 0.f);
        #pragma unroll
        for (int c4 = 0; c4 < 4; c4++) {
            // 4 loads of this chunk
            #pragma unroll
            for (int j = 0; j < 4; j++) {
                const int cc = c4 * 4 + j;
                const float4 v = __ldcs(reinterpret_cast<const float4*>(p + (size_t)cc * HW));
                acc.x += v.x; acc.y += v.y; acc.z += v.z; acc.w += v.w;
            }
            // one store batch of the previous patch, hidden under load stalls
            if (it > 0) {
                const float vv = sCoef[sm[c4]];
                float* o = obase + ((size_t)sm[c4] * HDIM + (h0 + sii[c4])) * WDIM
                                 + (w0p + sjj[c4]);
                __stcs(reinterpret_cast<float4*>(o), make_float4(vv, vv, vv, vv));
            }
        }
        sPart[t] = acc;
        __syncthreads();

        if (t < 64) {
            const float4 a0 = sPart[t];
            const float4 a1 = sPart[t + 64];
            const float4 a2 = sPart[t + 128];
            const float4 a3 = sPart[t + 192];
            float4 m4;
            m4.x = a0.x + a1.x + a2.x + a3.x;
            m4.y = a0.y + a1.y + a2.y + a3.y;
            m4.z = a0.z + a1.z + a2.z + a3.z;
            m4.w = a0.w + a1.w + a2.w + a3.w;

            const int pb = pi * 16 + pj4;
            float part[NM];
            #pragma unroll
            for (int m = 0; m < NM; m++) {
                const float4 bq = __ldg(reinterpret_cast<const float4*>(bases + m * 256 + pb));
                part[m] = m4.x * bq.x + m4.y * bq.y + m4.z * bq.z + m4.w * bq.w;
            }
            #pragma unroll
            for (int m = 0; m < NM; m++) {
                #pragma unroll
                for (int off = 16; off; off >>= 1)
                    part[m] += __shfl_xor_sync(0xffffffffu, part[m], off);
            }
            if ((t & 31) == 0) {
                const int w = t >> 5;
                #pragma unroll
                for (int m = 0; m < NM; m++) sW[w][m] = part[m];
            }
        }
        __syncthreads();
        if (t < NM) sCoef[t] = (sW[0][t] + sW[1][t]) * (1.0f / (float)CDIM);
        __syncthreads();

        w0p = w0;
    }

    // epilogue: drain stores for the last patch
    #pragma unroll
    for (int k = 0; k < 4; k++) {
        const float vv = sCoef[sm[k]];
        float* o = obase + ((size_t)sm[k] * HDIM + (h0 + sii[k])) * WDIM
                         + (w0p + sjj[k]);
        __stcs(reinterpret_cast<float4*>(o), make_float4(vv, vv, vv, vv));
    }
}

extern "C" void kernel_launch(void* const* d_in, const int* in_sizes, int n_in,
                              void* d_out, int out_size) {
    const float* x     = (const float*)d_in[0];
    const float* bases = (const float*)d_in[1];
    float*       out   = (float*)d_out;
    dim3 grid(WDIM / (2 * PW), HDIM / PH, 16);   // 7 x 14 x 16 = 1568 CTAs
    msp_dct_kernel<<<grid, 256>>>(x, bases, out);
}

// round 8
// speedup vs baseline: 1.4247x; 1.4247x over previous
#include <cuda_runtime.h>
#include <cuda.h>
#include <cuda_bf16.h>
#include <cstdint>

#define PH    16
#define PW    16
#define NM    16
#define HDIM  224
#define WDIM  224
#define CDIM  64
#define HW    (HDIM * WDIM)
#define NBUF  4          // pipeline depth
#define CCH   8          // channels per chunk
#define NCHK  (CDIM / CCH)   // 8 chunks

// ---------------- device helpers ----------------
__device__ __forceinline__ uint32_t smem_u32(const void* p) {
    uint32_t a;
    asm("{ .reg .u64 t; cvta.to.shared.u64 t, %1; cvt.u32.u64 %0, t; }"
        : "=r"(a) : "l"(p));
    return a;
}
__device__ __forceinline__ void mbar_init(uint32_t a, uint32_t cnt) {
    asm volatile("mbarrier.init.shared.b64 [%0], %1;" :: "r"(a), "r"(cnt) : "memory");
}
__device__ __forceinline__ void mbar_expect_tx(uint32_t a, uint32_t bytes) {
    asm volatile("mbarrier.arrive.expect_tx.shared.b64 _, [%0], %1;"
                 :: "r"(a), "r"(bytes) : "memory");
}
__device__ __forceinline__ void mbar_wait(uint32_t a, uint32_t phase) {
    asm volatile(
        "{\n\t.reg .pred P;\n"
        "W_%=:\n\t"
        "mbarrier.try_wait.parity.acquire.cta.shared::cta.b64 P, [%0], %1, 0x989680;\n\t"
        "@P bra D_%=;\n\t"
        "bra W_%=;\n"
        "D_%=:\n\t}"
        :: "r"(a), "r"(phase) : "memory");
}
__device__ __forceinline__ void tma_ld3d(uint32_t dst, const CUtensorMap* m,
                                         int cx, int cy, int cz, uint32_t mbar) {
    asm volatile(
        "cp.async.bulk.tensor.3d.shared::cta.global.tile.mbarrier::complete_tx::bytes "
        "[%0], [%1, {%2, %3, %4}], [%5];"
        :: "r"(dst), "l"(m), "r"(cx), "r"(cy), "r"(cz), "r"(mbar) : "memory");
}

// ---------------- TMA-pipelined fused kernel ----------------
__global__ __launch_bounds__(256, 6)
void msp_dct_tma_kernel(const __grid_constant__ CUtensorMap tmap,
                        const float* __restrict__ bases,
                        float* __restrict__ out) {
    __shared__ alignas(128) float sBuf[NBUF][CCH * 256];   // 32 KB
    __shared__ alignas(8) unsigned long long mbar[NBUF];
    __shared__ float sRed[8][NM];
    __shared__ float sCoef[NM];

    const int t  = threadIdx.x;        // t = pi*16 + pj (one pixel per thread)
    const int pw = blockIdx.x;
    const int ph = blockIdx.y;
    const int b  = blockIdx.z;
    const int h0 = ph * PH;
    const int w0 = pw * PW;
    const int cbase = b * CDIM;

    if (t == 0) {
        #pragma unroll
        for (int i = 0; i < NBUF; i++) mbar_init(smem_u32(&mbar[i]), 1);
        asm volatile("fence.proxy.async.shared::cta;" ::: "memory");
    }
    __syncthreads();

    if (t == 0) {
        #pragma unroll
        for (int i = 0; i < NBUF; i++) {
            mbar_expect_tx(smem_u32(&mbar[i]), CCH * 256 * 4);
            tma_ld3d(smem_u32(&sBuf[i][0]), &tmap, w0, h0, cbase + i * CCH,
                     smem_u32(&mbar[i]));
        }
    }

    // ---- pipelined channel sum ----
    float sum = 0.f;
    #pragma unroll
    for (int k = 0; k < NCHK; k++) {
        const int slot = k & (NBUF - 1);
        mbar_wait(smem_u32(&mbar[slot]), (k >> 2) & 1);
        #pragma unroll
        for (int j = 0; j < CCH; j++)
            sum += sBuf[slot][j * 256 + t];
        __syncthreads();                         // buffer fully consumed
        if (k + NBUF < NCHK && t == 0) {
            mbar_expect_tx(smem_u32(&mbar[slot]), CCH * 256 * 4);
            tma_ld3d(smem_u32(&sBuf[slot][0]), &tmap, w0, h0,
                     cbase + (k + NBUF) * CCH, smem_u32(&mbar[slot]));
        }
    }

    // ---- DCT: all 256 threads hold one pixel; reduce over block ----
    const int warp = t >> 5, lane = t & 31;
    #pragma unroll
    for (int half = 0; half < 2; half++) {
        float part[8];
        #pragma unroll
        for (int m = 0; m < 8; m++)
            part[m] = sum * __ldg(bases + (half * 8 + m) * 256 + t);
        #pragma unroll
        for (int m = 0; m < 8; m++) {
            #pragma unroll
            for (int off = 16; off; off >>= 1)
                part[m] += __shfl_xor_sync(0xffffffffu, part[m], off);
        }
        if (lane == 0) {
            #pragma unroll
            for (int m = 0; m < 8; m++) sRed[warp][half * 8 + m] = part[m];
        }
    }
    __syncthreads();
    if (t < NM) {
        float c = 0.f;
        #pragma unroll
        for (int w = 0; w < 8; w++) c += sRed[w][t];
        sCoef[t] = c * (1.0f / (float)CDIM);
    }
    __syncthreads();

    // ---- broadcast stores (R3 phase 3) ----
    #pragma unroll
    for (int k = 0; k < 4; k++) {
        const int idx = t + k * 256;
        const int m   = idx >> 6;
        const int gg  = idx & 63;
        const int ii  = gg >> 2;
        const int jj  = (gg & 3) * 4;
        const float v = sCoef[m];
        float* o = out + ((size_t)(b * NM + m) * HDIM + (h0 + ii)) * WDIM
                       + (w0 + jj);
        __stcs(reinterpret_cast<float4*>(o), make_float4(v, v, v, v));
    }
}

// ---------------- fallback: R3 LDG kernel (proven 45.5us) ----------------
__global__ __launch_bounds__(256, 6)
void msp_dct_ldg_kernel(const float* __restrict__ x,
                        const float* __restrict__ bases,
                        float* __restrict__ out) {
    __shared__ float4 sPart[256];
    __shared__ float  sW[2][NM];
    __shared__ float  sCoef[NM];

    const int t  = threadIdx.x;
    const int pw = blockIdx.x;
    const int ph = blockIdx.y;
    const int b  = blockIdx.z;
    const int h0 = ph * PH;
    const int w0 = pw * PW;

    const int g   = t & 63;
    const int pi  = g >> 2;
    const int pj4 = (g & 3) * 4;
    const int csl = t >> 6;
    {
        const float* p = x + ((size_t)(b * CDIM + csl * 16)) * HW
                           + (size_t)(h0 + pi) * WDIM + (w0 + pj4);
        float4 acc = make_float4(0.f, 0.f, 0.f, 0.f);
        #pragma unroll
        for (int cc = 0; cc < 16; cc++) {
            const float4 v = __ldcs(reinterpret_cast<const float4*>(p + (size_t)cc * HW));
            acc.x += v.x; acc.y += v.y; acc.z += v.z; acc.w += v.w;
        }
        sPart[t] = acc;
    }
    __syncthreads();

    if (t < 64) {
        const float4 a0 = sPart[t];
        const float4 a1 = sPart[t + 64];
        const float4 a2 = sPart[t + 128];
        const float4 a3 = sPart[t + 192];
        float4 m4;
        m4.x = a0.x + a1.x + a2.x + a3.x;
        m4.y = a0.y + a1.y + a2.y + a3.y;
        m4.z = a0.z + a1.z + a2.z + a3.z;
        m4.w = a0.w + a1.w + a2.w + a3.w;

        const int pb = pi * 16 + pj4;
        float part[NM];
        #pragma unroll
        for (int m = 0; m < NM; m++) {
            const float4 bq = __ldg(reinterpret_cast<const float4*>(bases + m * 256 + pb));
            part[m] = m4.x * bq.x + m4.y * bq.y + m4.z * bq.z + m4.w * bq.w;
        }
        #pragma unroll
        for (int m = 0; m < NM; m++) {
            #pragma unroll
            for (int off = 16; off; off >>= 1)
                part[m] += __shfl_xor_sync(0xffffffffu, part[m], off);
        }
        if ((t & 31) == 0) {
            const int w = t >> 5;
            #pragma unroll
            for (int m = 0; m < NM; m++) sW[w][m] = part[m];
        }
    }
    __syncthreads();
    if (t < NM) sCoef[t] = (sW[0][t] + sW[1][t]) * (1.0f / (float)CDIM);
    __syncthreads();

    #pragma unroll
    for (int k = 0; k < 4; k++) {
        const int idx = t + k * 256;
        const int m   = idx >> 6;
        const int gg  = idx & 63;
        const int ii  = gg >> 2;
        const int jj  = (gg & 3) * 4;
        const float v = sCoef[m];
        float* o = out + ((size_t)(b * NM + m) * HDIM + (h0 + ii)) * WDIM
                       + (w0 + jj);
        __stcs(reinterpret_cast<float4*>(o), make_float4(v, v, v, v));
    }
}

// ---------------- host ----------------
typedef CUresult (*EncodeFn)(CUtensorMap*, CUtensorMapDataType, cuuint32_t, void*,
                             const cuuint64_t*, const cuuint64_t*, const cuuint32_t*,
                             const cuuint32_t*, CUtensorMapInterleave, CUtensorMapSwizzle,
                             CUtensorMapL2promotion, CUtensorMapFloatOOBfill);

extern "C" void kernel_launch(void* const* d_in, const int* in_sizes, int n_in,
                              void* d_out, int out_size) {
    const float* x     = (const float*)d_in[0];
    const float* bases = (const float*)d_in[1];
    float*       out   = (float*)d_out;
    dim3 grid(WDIM / PW, HDIM / PH, 16);   // 14 x 14 x 16

    void* fp = nullptr;
    cudaDriverEntryPointQueryResult qr;
    cudaGetDriverEntryPoint("cuTensorMapEncodeTiled", &fp, cudaEnableDefault, &qr);

    bool ok = (fp != nullptr);
    CUtensorMap tmap;
    if (ok) {
        cuuint64_t dims[3]    = {WDIM, HDIM, 16 * CDIM};
        cuuint64_t strides[2] = {WDIM * 4ull, (cuuint64_t)HW * 4ull};
        cuuint32_t box[3]     = {PW, PH, CCH};
        cuuint32_t es[3]      = {1, 1, 1};
        ok = (((EncodeFn)fp)(&tmap, CU_TENSOR_MAP_DATA_TYPE_FLOAT32, 3, (void*)x,
                             dims, strides, box, es,
                             CU_TENSOR_MAP_INTERLEAVE_NONE, CU_TENSOR_MAP_SWIZZLE_NONE,
                             CU_TENSOR_MAP_L2_PROMOTION_L2_128B,
                             CU_TENSOR_MAP_FLOAT_OOB_FILL_NONE) == CUDA_SUCCESS);
    }

    if (ok) msp_dct_tma_kernel<<<grid, 256>>>(tmap, bases, out);
    else    msp_dct_ldg_kernel<<<grid, 256>>>(x, bases, out);
}

// round 9
// speedup vs baseline: 1.4958x; 1.0499x over previous
#include <cuda_runtime.h>
#include <cuda.h>
#include <cuda_bf16.h>
#include <cstdint>

#define PH    16
#define PW    16
#define NM    16
#define HDIM  224
#define WDIM  224
#define CDIM  64
#define HW    (HDIM * WDIM)
#define NBUF  4
#define CCH   8                   // channels per chunk
#define NCHK  (CDIM / CCH)        // 8 chunks
#define SW    32                  // strip width (2 patches)
#define SPIX  (SW * PH)           // 512 pixels per strip
#define CHUNK_BYTES (CCH * SPIX * 4)   // 16 KB

// dynamic smem layout
#define OFF_BUF   0
#define OFF_MBAR  (NBUF * CHUNK_BYTES)          // 65536
#define OFF_RED   (OFF_MBAR + NBUF * 8)         // 65568
#define OFF_COEF  (OFF_RED + 16 * 2 * NM * 4)   // 67616
#define SMEM_DYN  69632                          // 68 KB -> 3 CTAs/SM

__device__ __forceinline__ uint32_t smem_u32(const void* p) {
    uint32_t a;
    asm("{ .reg .u64 t; cvta.to.shared.u64 t, %1; cvt.u32.u64 %0, t; }"
        : "=r"(a) : "l"(p));
    return a;
}
__device__ __forceinline__ void mbar_init(uint32_t a, uint32_t cnt) {
    asm volatile("mbarrier.init.shared.b64 [%0], %1;" :: "r"(a), "r"(cnt) : "memory");
}
__device__ __forceinline__ void mbar_expect_tx(uint32_t a, uint32_t bytes) {
    asm volatile("mbarrier.arrive.expect_tx.shared.b64 _, [%0], %1;"
                 :: "r"(a), "r"(bytes) : "memory");
}
__device__ __forceinline__ void mbar_wait(uint32_t a, uint32_t phase) {
    asm volatile(
        "{\n\t.reg .pred P;\n"
        "W_%=:\n\t"
        "mbarrier.try_wait.parity.acquire.cta.shared::cta.b64 P, [%0], %1, 0x989680;\n\t"
        "@P bra D_%=;\n\t"
        "bra W_%=;\n"
        "D_%=:\n\t}"
        :: "r"(a), "r"(phase) : "memory");
}
__device__ __forceinline__ void tma_ld3d(uint32_t dst, const CUtensorMap* m,
                                         int cx, int cy, int cz, uint32_t mbar) {
    asm volatile(
        "cp.async.bulk.tensor.3d.shared::cta.global.tile.mbarrier::complete_tx::bytes "
        "[%0], [%1, {%2, %3, %4}], [%5];"
        :: "r"(dst), "l"(m), "r"(cx), "r"(cy), "r"(cz), "r"(mbar) : "memory");
}

// ============ TMA strip kernel: CTA = 32x16 strip, full-line boxes ==========
__global__ __launch_bounds__(512, 3)
void msp_dct_tma_kernel(const __grid_constant__ CUtensorMap tmap,
                        const float* __restrict__ bases,
                        float* __restrict__ out) {
    extern __shared__ char dyn[];
    float* sBuf  = reinterpret_cast<float*>(dyn + OFF_BUF);
    unsigned long long* mbar = reinterpret_cast<unsigned long long*>(dyn + OFF_MBAR);
    float* sRed  = reinterpret_cast<float*>(dyn + OFF_RED);   // [warp][patch][m]
    float* sCoef = reinterpret_cast<float*>(dyn + OFF_COEF);  // [patch][m]

    const int t   = threadIdx.x;           // t = row*32 + col
    const int w0  = blockIdx.x * SW;
    const int h0  = blockIdx.y * PH;
    const int b   = blockIdx.z;
    const int cb  = b * CDIM;

    if (t == 0) {
        #pragma unroll
        for (int i = 0; i < NBUF; i++) mbar_init(smem_u32(&mbar[i]), 1);
        asm volatile("fence.proxy.async.shared::cta;" ::: "memory");
    }
    __syncthreads();

    if (t == 0) {
        #pragma unroll
        for (int i = 0; i < NBUF; i++) {
            mbar_expect_tx(smem_u32(&mbar[i]), CHUNK_BYTES);
            tma_ld3d(smem_u32(&sBuf[i * CCH * SPIX]), &tmap,
                     w0, h0, cb + i * CCH, smem_u32(&mbar[i]));
        }
    }

    // ---- pipelined channel sum ----
    float sum = 0.f;
    #pragma unroll
    for (int k = 0; k < NCHK; k++) {
        const int slot = k & (NBUF - 1);
        mbar_wait(smem_u32(&mbar[slot]), (k >> 2) & 1);
        const float* buf = &sBuf[slot * CCH * SPIX];
        #pragma unroll
        for (int j = 0; j < CCH; j++)
            sum += buf[j * SPIX + t];
        __syncthreads();
        if (k + NBUF < NCHK && t == 0) {
            mbar_expect_tx(smem_u32(&mbar[slot]), CHUNK_BYTES);
            tma_ld3d(smem_u32(&sBuf[slot * CCH * SPIX]), &tmap,
                     w0, h0, cb + (k + NBUF) * CCH, smem_u32(&mbar[slot]));
        }
    }

    // ---- DCT: warp = one row of 32 cols (two patches split at lane 16) ----
    const int warp = t >> 5;               // row 0..15
    const int lane = t & 31;
    const int pb   = warp * 16 + (lane & 15);   // pixel index within own patch
    #pragma unroll
    for (int half = 0; half < 2; half++) {
        float part[8];
        #pragma unroll
        for (int m = 0; m < 8; m++)
            part[m] = sum * __ldg(bases + (half * 8 + m) * 256 + pb);
        #pragma unroll
        for (int m = 0; m < 8; m++) {
            part[m] += __shfl_xor_sync(0xffffffffu, part[m], 1);
            part[m] += __shfl_xor_sync(0xffffffffu, part[m], 2);
            part[m] += __shfl_xor_sync(0xffffffffu, part[m], 4);
            part[m] += __shfl_xor_sync(0xffffffffu, part[m], 8);
        }
        if ((lane & 15) == 0) {
            const int pidx = lane >> 4;
            #pragma unroll
            for (int m = 0; m < 8; m++)
                sRed[(warp * 2 + pidx) * NM + half * 8 + m] = part[m];
        }
    }
    __syncthreads();
    if (t < 32) {
        const int m = t & 15, pidx = t >> 4;
        float c = 0.f;
        #pragma unroll
        for (int w = 0; w < 16; w++) c += sRed[(w * 2 + pidx) * NM + m];
        sCoef[pidx * NM + m] = c * (1.0f / (float)CDIM);
    }
    __syncthreads();

    // ---- broadcast stores: 2048 float4, full-line warp segments ----
    #pragma unroll
    for (int k = 0; k < 4; k++) {
        const int idx = t + k * 512;        // 0..2047
        const int m   = idx >> 7;           // 128 quads per base map
        const int gg  = idx & 127;
        const int rr  = gg >> 3;            // row 0..15
        const int cq  = gg & 7;             // col quad 0..7
        const float v = sCoef[(cq >> 2) * NM + m];
        float* o = out + ((size_t)(b * NM + m) * HDIM + (h0 + rr)) * WDIM
                       + (w0 + cq * 4);
        __stcs(reinterpret_cast<float4*>(o), make_float4(v, v, v, v));
    }
}

// ============ fallback: R3 LDG kernel (proven 45.5us) ============
__global__ __launch_bounds__(256, 6)
void msp_dct_ldg_kernel(const float* __restrict__ x,
                        const float* __restrict__ bases,
                        float* __restrict__ out) {
    __shared__ float4 sPart[256];
    __shared__ float  sW[2][NM];
    __shared__ float  sCoef[NM];

    const int t  = threadIdx.x;
    const int pw = blockIdx.x;
    const int ph = blockIdx.y;
    const int b  = blockIdx.z;
    const int h0 = ph * PH;
    const int w0 = pw * PW;

    const int g   = t & 63;
    const int pi  = g >> 2;
    const int pj4 = (g & 3) * 4;
    const int csl = t >> 6;
    {
        const float* p = x + ((size_t)(b * CDIM + csl * 16)) * HW
                           + (size_t)(h0 + pi) * WDIM + (w0 + pj4);
        float4 acc = make_float4(0.f, 0.f, 0.f, 0.f);
        #pragma unroll
        for (int cc = 0; cc < 16; cc++) {
            const float4 v = __ldcs(reinterpret_cast<const float4*>(p + (size_t)cc * HW));
            acc.x += v.x; acc.y += v.y; acc.z += v.z; acc.w += v.w;
        }
        sPart[t] = acc;
    }
    __syncthreads();

    if (t < 64) {
        const float4 a0 = sPart[t];
        const float4 a1 = sPart[t + 64];
        const float4 a2 = sPart[t + 128];
        const float4 a3 = sPart[t + 192];
        float4 m4;
        m4.x = a0.x + a1.x + a2.x + a3.x;
        m4.y = a0.y + a1.y + a2.y + a3.y;
        m4.z = a0.z + a1.z + a2.z + a3.z;
        m4.w = a0.w + a1.w + a2.w + a3.w;

        const int pb = pi * 16 + pj4;
        float part[NM];
        #pragma unroll
        for (int m = 0; m < NM; m++) {
            const float4 bq = __ldg(reinterpret_cast<const float4*>(bases + m * 256 + pb));
            part[m] = m4.x * bq.x + m4.y * bq.y + m4.z * bq.z + m4.w * bq.w;
        }
        #pragma unroll
        for (int m = 0; m < NM; m++) {
            #pragma unroll
            for (int off = 16; off; off >>= 1)
                part[m] += __shfl_xor_sync(0xffffffffu, part[m], off);
        }
        if ((t & 31) == 0) {
            const int w = t >> 5;
            #pragma unroll
            for (int m = 0; m < NM; m++) sW[w][m] = part[m];
        }
    }
    __syncthreads();
    if (t < NM) sCoef[t] = (sW[0][t] + sW[1][t]) * (1.0f / (float)CDIM);
    __syncthreads();

    #pragma unroll
    for (int k = 0; k < 4; k++) {
        const int idx = t + k * 256;
        const int m   = idx >> 6;
        const int gg  = idx & 63;
        const int ii  = gg >> 2;
        const int jj  = (gg & 3) * 4;
        const float v = sCoef[m];
        float* o = out + ((size_t)(b * NM + m) * HDIM + (h0 + ii)) * WDIM
                       + (w0 + jj);
        __stcs(reinterpret_cast<float4*>(o), make_float4(v, v, v, v));
    }
}

// ---------------- host ----------------
typedef CUresult (*EncodeFn)(CUtensorMap*, CUtensorMapDataType, cuuint32_t, void*,
                             const cuuint64_t*, const cuuint64_t*, const cuuint32_t*,
                             const cuuint32_t*, CUtensorMapInterleave, CUtensorMapSwizzle,
                             CUtensorMapL2promotion, CUtensorMapFloatOOBfill);

extern "C" void kernel_launch(void* const* d_in, const int* in_sizes, int n_in,
                              void* d_out, int out_size) {
    const float* x     = (const float*)d_in[0];
    const float* bases = (const float*)d_in[1];
    float*       out   = (float*)d_out;

    void* fp = nullptr;
    cudaDriverEntryPointQueryResult qr;
    cudaGetDriverEntryPoint("cuTensorMapEncodeTiled", &fp, cudaEnableDefault, &qr);

    bool ok = (fp != nullptr);
    CUtensorMap tmap;
    if (ok) {
        cuuint64_t dims[3]    = {WDIM, HDIM, 16 * CDIM};
        cuuint64_t strides[2] = {WDIM * 4ull, (cuuint64_t)HW * 4ull};
        cuuint32_t box[3]     = {SW, PH, CCH};
        cuuint32_t es[3]      = {1, 1, 1};
        ok = (((EncodeFn)fp)(&tmap, CU_TENSOR_MAP_DATA_TYPE_FLOAT32, 3, (void*)x,
                             dims, strides, box, es,
                             CU_TENSOR_MAP_INTERLEAVE_NONE, CU_TENSOR_MAP_SWIZZLE_NONE,
                             CU_TENSOR_MAP_L2_PROMOTION_L2_256B,
                             CU_TENSOR_MAP_FLOAT_OOB_FILL_NONE) == CUDA_SUCCESS);
    }
    if (ok) {
        ok = (cudaFuncSetAttribute(msp_dct_tma_kernel,
                                   cudaFuncAttributeMaxDynamicSharedMemorySize,
                                   SMEM_DYN) == cudaSuccess);
    }

    if (ok) {
        dim3 grid(WDIM / SW, HDIM / PH, 16);     // 7 x 14 x 16
        msp_dct_tma_kernel<<<grid, 512, SMEM_DYN>>>(tmap, bases, out);
    } else {
        dim3 grid(WDIM / PW, HDIM / PH, 16);     // 14 x 14 x 16
        msp_dct_ldg_kernel<<<grid, 256>>>(x, bases, out);
    }
}